// round 15
// baseline (speedup 1.0000x reference)
#include <cuda_runtime.h>
#include <cuda_fp16.h>
#include <cstdint>

#define NN 100000
#define EE 1600000
#define DH 128
#define DOUT 40
#define BN_EPS 1e-5f
#define HST 68   // half2 stride per row in GEMM smem (4B units), conflict-free
#define SCANB 98 // (NN + 1023) / 1024
#define GEMMGRID 782

// ===================== scratch ==============================================
__device__ __half g_x0h[NN * DH];   // x0 residual, fp16 (== fp16 h0)
__device__ __half g_hH[NN * DH];    // current h for SPMM gather (fp16)
__device__ __half g_aggH[NN * DH];  // SPMM output (fp16) -> GEMM A
__device__ float  g_bB[NN * DH];    // z = GEMM output
__device__ int    g_deg[NN];
__device__ int    g_fill[NN];
__device__ float  g_dinv[NN];
__device__ int    g_rowptr[NN + 1];
__device__ int2   g_edge[EE];       // {src, float bits of val}
__device__ int    g_bsum[128];
__device__ float  g_stats[2 * DH];
__device__ float  g_scale[DH];
__device__ float  g_shift[DH];
__device__ int    g_done;           // GEMM block-arrival counter (self-resetting)

// ===================== graph build ==========================================
__global__ void k_zero_build() {
    int i = blockIdx.x * 256 + threadIdx.x;
    if (i < NN) { g_deg[i] = 0; g_fill[i] = 0; }
}

__global__ void k_degree(const int* __restrict__ ei) {
    int e = blockIdx.x * 256 + threadIdx.x;
    if (e < EE) atomicAdd(&g_deg[ei[EE + e]], 1);
}

__global__ void k_scan_part() {
    __shared__ int ws[8];
    int t = threadIdx.x, b = blockIdx.x;
    int base = b * 1024 + t * 4;
    int4 d = make_int4(0, 0, 0, 0);
    if (base + 3 < NN) d = *(const int4*)&g_deg[base];
    else {
        if (base + 0 < NN) d.x = g_deg[base + 0];
        if (base + 1 < NN) d.y = g_deg[base + 1];
        if (base + 2 < NN) d.z = g_deg[base + 2];
    }
    float4 dv;
    dv.x = d.x > 0 ? rsqrtf((float)d.x) : 0.f;
    dv.y = d.y > 0 ? rsqrtf((float)d.y) : 0.f;
    dv.z = d.z > 0 ? rsqrtf((float)d.z) : 0.f;
    dv.w = d.w > 0 ? rsqrtf((float)d.w) : 0.f;
    if (base + 3 < NN) *(float4*)&g_dinv[base] = dv;
    else {
        if (base + 0 < NN) g_dinv[base + 0] = dv.x;
        if (base + 1 < NN) g_dinv[base + 1] = dv.y;
        if (base + 2 < NN) g_dinv[base + 2] = dv.z;
    }
    int s = d.x + d.y + d.z + d.w;
    int lane = t & 31, wid = t >> 5;
    int sc = s;
#pragma unroll
    for (int o = 1; o < 32; o <<= 1) {
        int u = __shfl_up_sync(0xffffffffu, sc, o);
        if (lane >= o) sc += u;
    }
    if (lane == 31) ws[wid] = sc;
    __syncthreads();
    if (t < 8) {
        int v = ws[t];
#pragma unroll
        for (int o = 1; o < 8; o <<= 1) {
            int u = __shfl_up_sync(0xffu, v, o);
            if (t >= o) v += u;
        }
        ws[t] = v;
    }
    __syncthreads();
    int excl = sc - s + (wid ? ws[wid - 1] : 0);
    int4 rp;
    rp.x = excl; rp.y = excl + d.x; rp.z = rp.y + d.y; rp.w = rp.z + d.z;
    if (base + 3 < NN) *(int4*)&g_rowptr[base] = rp;
    else {
        if (base + 0 < NN) g_rowptr[base + 0] = rp.x;
        if (base + 1 < NN) g_rowptr[base + 1] = rp.y;
        if (base + 2 < NN) g_rowptr[base + 2] = rp.z;
    }
    if (t == 255) g_bsum[b] = excl + s;
}

__global__ void k_scan_add2() {
    __shared__ int soff;
    int t = threadIdx.x, b = blockIdx.x;
    if (t < 32) {
        int acc = 0, tot = 0;
#pragma unroll
        for (int i = 0; i < 4; ++i) {
            int idx = i * 32 + t;
            int v = (idx < SCANB) ? g_bsum[idx] : 0;
            tot += v;
            if (idx < b) acc += v;
        }
#pragma unroll
        for (int o = 16; o; o >>= 1) {
            acc += __shfl_xor_sync(0xffffffffu, acc, o);
            tot += __shfl_xor_sync(0xffffffffu, tot, o);
        }
        if (t == 0) {
            soff = acc;
            if (b == 0) g_rowptr[NN] = tot;
        }
    }
    __syncthreads();
    int off = soff;
    if (off == 0) return;
    int base = b * 1024 + t * 4;
    if (base + 3 < NN) {
        int4 rp = *(const int4*)&g_rowptr[base];
        rp.x += off; rp.y += off; rp.z += off; rp.w += off;
        *(int4*)&g_rowptr[base] = rp;
    } else {
        for (int i = 0; i < 4; ++i)
            if (base + i < NN) g_rowptr[base + i] += off;
    }
}

__global__ void k_fill(const int* __restrict__ ei) {
    int e = blockIdx.x * 256 + threadIdx.x;
    if (e >= EE) return;
    int r = ei[e];
    int c = ei[EE + e];
    int p = g_rowptr[c] + atomicAdd(&g_fill[c], 1);
    float v = g_dinv[r] * g_dinv[c];
    g_edge[p] = make_int2(r, __float_as_int(v));
}

// ===================== split-fp16 mma.sync GEMM =============================
__device__ __forceinline__ void split_h2(float x, float y, uint32_t& hi, uint32_t& lo) {
    __half2 h = __floats2half2_rn(x, y);
    float2 hf = __half22float2(h);
    __half2 l = __floats2half2_rn(x - hf.x, y - hf.y);
    hi = *(uint32_t*)&h;
    lo = *(uint32_t*)&l;
}

__device__ __forceinline__ void mma16(float* d, const uint32_t* a, uint32_t b0, uint32_t b1) {
    asm volatile(
        "mma.sync.aligned.m16n8k16.row.col.f32.f16.f16.f32 "
        "{%0,%1,%2,%3}, {%4,%5,%6,%7}, {%8,%9}, {%0,%1,%2,%3};"
        : "+f"(d[0]), "+f"(d[1]), "+f"(d[2]), "+f"(d[3])
        : "r"(a[0]), "r"(a[1]), "r"(a[2]), "r"(a[3]), "r"(b0), "r"(b1));
}

#define GEMM_SMEM_F (4 * 128 * HST * 4 + 3 * 128 * 4)
#define GEMM_SMEM_H (3 * 128 * HST * 4 + 3 * 128 * 4)

template <bool AHALF>
__global__ __launch_bounds__(256)
void k_gemm_t(const void* __restrict__ Ain, const float* __restrict__ W,
              const float* __restrict__ bias, float* __restrict__ Z,
              const float* __restrict__ gamma, const float* __restrict__ beta,
              int nrows) {
    extern __shared__ uint32_t smu[];
    uint32_t* sAh = smu;
    uint32_t* sAl = AHALF ? smu : smu + 128 * HST;
    uint32_t* sBh = smu + (AHALF ? 1 : 2) * 128 * HST;
    uint32_t* sBl = sBh + 128 * HST;
    float* sSum  = (float*)(sBl + 128 * HST);
    float* sSq   = sSum + 128;
    float* sBias = sSq + 128;
    __shared__ int sLast;

    const int tid = threadIdx.x;
    const int wid = tid >> 5, lane = tid & 31;
    const int rowBase = blockIdx.x * 128;
    const int r = lane >> 2, c = lane & 3;

    if (AHALF) {
        const uint2* A2 = (const uint2*)Ain;
#pragma unroll
        for (int it = 0; it < 16; ++it) {
            int vec = tid + it * 256;
            int row = vec >> 5, q = vec & 31;
            int gr = rowBase + row;
            uint2 u = make_uint2(0u, 0u);
            if (gr < nrows) u = A2[(size_t)gr * 32 + q];
            *(uint2*)&sAh[row * HST + 2 * q] = u;
        }
    } else {
        const float4* A4 = (const float4*)Ain;
#pragma unroll
        for (int it = 0; it < 16; ++it) {
            int vec = tid + it * 256;
            int row = vec >> 5, q = vec & 31;
            int gr = rowBase + row;
            float4 v = make_float4(0.f, 0.f, 0.f, 0.f);
            if (gr < nrows) v = A4[(size_t)gr * 32 + q];
            uint32_t h0, l0, h1, l1;
            split_h2(v.x, v.y, h0, l0);
            split_h2(v.z, v.w, h1, l1);
            int idx = row * HST + 2 * q;
            *(uint2*)&sAh[idx] = make_uint2(h0, h1);
            *(uint2*)&sAl[idx] = make_uint2(l0, l1);
        }
    }
    const float4* W4 = (const float4*)W;
#pragma unroll
    for (int it = 0; it < 16; ++it) {
        int vec = tid + it * 256;
        int row = vec >> 5, q = vec & 31;
        float4 v = W4[vec];
        uint32_t h0, l0, h1, l1;
        split_h2(v.x, v.y, h0, l0);
        split_h2(v.z, v.w, h1, l1);
        int idx = row * HST + 2 * q;
        *(uint2*)&sBh[idx] = make_uint2(h0, h1);
        *(uint2*)&sBl[idx] = make_uint2(l0, l1);
    }
    if (tid < 128) { sSum[tid] = 0.f; sSq[tid] = 0.f; sBias[tid] = bias[tid]; }
    __syncthreads();

    const int wm = wid & 3, wn = wid >> 2;
    float acc[2][8][4];
#pragma unroll
    for (int mt = 0; mt < 2; ++mt)
#pragma unroll
        for (int nt = 0; nt < 8; ++nt)
#pragma unroll
            for (int i = 0; i < 4; ++i) acc[mt][nt][i] = 0.f;

#pragma unroll 1
    for (int ks = 0; ks < 8; ++ks) {
        const int kb = ks * 8 + c;
        uint32_t ah[2][4], al[2][4];
#pragma unroll
        for (int mt = 0; mt < 2; ++mt) {
            int ba = (wm * 32 + mt * 16 + r) * HST + kb;
            ah[mt][0] = sAh[ba];
            ah[mt][1] = sAh[ba + 8 * HST];
            ah[mt][2] = sAh[ba + 4];
            ah[mt][3] = sAh[ba + 8 * HST + 4];
            if (!AHALF) {
                al[mt][0] = sAl[ba];
                al[mt][1] = sAl[ba + 8 * HST];
                al[mt][2] = sAl[ba + 4];
                al[mt][3] = sAl[ba + 8 * HST + 4];
            }
        }
#pragma unroll
        for (int nt = 0; nt < 8; ++nt) {
            int bb = (wn * 64 + nt * 8 + r) * HST + kb;
            uint32_t bh0 = sBh[bb], bh1 = sBh[bb + 4];
            uint32_t bl0 = sBl[bb], bl1 = sBl[bb + 4];
#pragma unroll
            for (int mt = 0; mt < 2; ++mt) {
                mma16(acc[mt][nt], ah[mt], bh0, bh1);
                mma16(acc[mt][nt], ah[mt], bl0, bl1);
                if (!AHALF) mma16(acc[mt][nt], al[mt], bh0, bh1);
            }
        }
    }

    float cs[16], cq[16];
#pragma unroll
    for (int i = 0; i < 16; ++i) { cs[i] = 0.f; cq[i] = 0.f; }

#pragma unroll
    for (int nt = 0; nt < 8; ++nt) {
        int C0 = wn * 64 + nt * 8 + 2 * c;
        float b0 = sBias[C0], b1 = sBias[C0 + 1];
#pragma unroll
        for (int mt = 0; mt < 2; ++mt) {
            int R0 = rowBase + wm * 32 + mt * 16 + r;
            int R1 = R0 + 8;
            if (R0 < nrows) {
                float z0 = acc[mt][nt][0] + b0;
                float z1 = acc[mt][nt][1] + b1;
                *(float2*)&Z[(size_t)R0 * 128 + C0] = make_float2(z0, z1);
                cs[2 * nt] += z0; cq[2 * nt] += z0 * z0;
                cs[2 * nt + 1] += z1; cq[2 * nt + 1] += z1 * z1;
            }
            if (R1 < nrows) {
                float z2 = acc[mt][nt][2] + b0;
                float z3 = acc[mt][nt][3] + b1;
                *(float2*)&Z[(size_t)R1 * 128 + C0] = make_float2(z2, z3);
                cs[2 * nt] += z2; cq[2 * nt] += z2 * z2;
                cs[2 * nt + 1] += z3; cq[2 * nt + 1] += z3 * z3;
            }
        }
    }
#pragma unroll
    for (int o = 4; o <= 16; o <<= 1) {
#pragma unroll
        for (int i = 0; i < 16; ++i) {
            cs[i] += __shfl_xor_sync(0xffffffffu, cs[i], o);
            cq[i] += __shfl_xor_sync(0xffffffffu, cq[i], o);
        }
    }
    if (r == 0) {
#pragma unroll
        for (int nt = 0; nt < 8; ++nt) {
            int C0 = wn * 64 + nt * 8 + 2 * c;
            atomicAdd(&sSum[C0],     cs[2 * nt]);
            atomicAdd(&sSum[C0 + 1], cs[2 * nt + 1]);
            atomicAdd(&sSq[C0],      cq[2 * nt]);
            atomicAdd(&sSq[C0 + 1],  cq[2 * nt + 1]);
        }
    }
    __syncthreads();
    if (tid < 128) {
        atomicAdd(&g_stats[tid], sSum[tid]);
        atomicAdd(&g_stats[128 + tid], sSq[tid]);
    }

    // last-block-done: final block computes scale/shift (== old k_bnprep)
    __threadfence();
    __syncthreads();
    if (tid == 0) {
        int old = atomicAdd(&g_done, 1);
        sLast = (old == GEMMGRID - 1) ? 1 : 0;
    }
    __syncthreads();
    if (sLast) {
        __threadfence();   // acquire: all blocks' stats atomics visible
        if (tid < DH) {
            float s = g_stats[tid];
            float q = g_stats[128 + tid];
            float mu = s * (1.0f / (float)NN);
            float var = q * (1.0f / (float)NN) - mu * mu;
            float rs = rsqrtf(var + BN_EPS);
            float sc = gamma[tid] * rs;
            g_scale[tid] = sc;
            g_shift[tid] = beta[tid] - mu * sc;
            g_stats[tid] = 0.f;
            g_stats[128 + tid] = 0.f;
        }
        if (tid == 0) g_done = 0;   // reset for the next GEMM launch
    }
}

// ========== fused BN/ReLU/residual; fp16 residual input =====================
__global__ void k_bnfused(const float4* __restrict__ Z, const uint2* __restrict__ X0,
                          uint2* __restrict__ OutH, int nvec) {
    int i = blockIdx.x * 256 + threadIdx.x;
    if (i >= nvec) return;
    int c4 = i & 31;
    float4 sc = ((const float4*)g_scale)[c4];
    float4 sh = ((const float4*)g_shift)[c4];
    float4 z = Z[i];
    float4 h;
    h.x = fmaxf(fmaf(z.x, sc.x, sh.x), 0.f);
    h.y = fmaxf(fmaf(z.y, sc.y, sh.y), 0.f);
    h.z = fmaxf(fmaf(z.z, sc.z, sh.z), 0.f);
    h.w = fmaxf(fmaf(z.w, sc.w, sh.w), 0.f);
    if (X0) {
        uint2 u = X0[i];
        float2 x0 = __half22float2(*(__half2*)&u.x);
        float2 x1 = __half22float2(*(__half2*)&u.y);
        h.x += x0.x; h.y += x0.y; h.z += x1.x; h.w += x1.y;
    }
    __half2 p0 = __floats2half2_rn(h.x, h.y);
    __half2 p1 = __floats2half2_rn(h.z, h.w);
    uint2 u;
    u.x = *(uint32_t*)&p0;
    u.y = *(uint32_t*)&p1;
    OutH[i] = u;
}

// ===== SPMM: warp/node, shfl broadcast, fp16 gather, fp32 acc, MLP=4 =======
__device__ __forceinline__ void spmm_fma(float4& acc, float vj, uint2 u) {
    float2 f0 = __half22float2(*(__half2*)&u.x);
    float2 f1 = __half22float2(*(__half2*)&u.y);
    acc.x = fmaf(vj, f0.x, acc.x);
    acc.y = fmaf(vj, f0.y, acc.y);
    acc.z = fmaf(vj, f1.x, acc.z);
    acc.w = fmaf(vj, f1.y, acc.w);
}

__global__ void k_spmm(const uint2* __restrict__ H, uint2* __restrict__ O) {
    int gt = blockIdx.x * 256 + threadIdx.x;
    int w = gt >> 5;
    int lane = gt & 31;
    if (w >= NN) return;
    int rp0 = g_rowptr[w], rp1 = g_rowptr[w + 1];
    float4 acc = make_float4(0.f, 0.f, 0.f, 0.f);
    for (int base = rp0; base < rp1; base += 32) {
        int nb = min(32, rp1 - base);
        int s = 0; float v = 0.f;
        if (lane < nb) {
            int2 e = g_edge[base + lane];
            s = e.x; v = __int_as_float(e.y);
        }
        int j = 0;
#pragma unroll 1
        for (; j + 4 <= nb; j += 4) {
            int s0 = __shfl_sync(0xffffffffu, s, j);
            int s1 = __shfl_sync(0xffffffffu, s, j + 1);
            int s2 = __shfl_sync(0xffffffffu, s, j + 2);
            int s3 = __shfl_sync(0xffffffffu, s, j + 3);
            float v0 = __shfl_sync(0xffffffffu, v, j);
            float v1 = __shfl_sync(0xffffffffu, v, j + 1);
            float v2 = __shfl_sync(0xffffffffu, v, j + 2);
            float v3 = __shfl_sync(0xffffffffu, v, j + 3);
            uint2 u0 = H[(size_t)s0 * 32 + lane];
            uint2 u1 = H[(size_t)s1 * 32 + lane];
            uint2 u2 = H[(size_t)s2 * 32 + lane];
            uint2 u3 = H[(size_t)s3 * 32 + lane];
            spmm_fma(acc, v0, u0);
            spmm_fma(acc, v1, u1);
            spmm_fma(acc, v2, u2);
            spmm_fma(acc, v3, u3);
        }
        for (; j < nb; ++j) {
            int sj = __shfl_sync(0xffffffffu, s, j);
            float vj = __shfl_sync(0xffffffffu, v, j);
            spmm_fma(acc, vj, H[(size_t)sj * 32 + lane]);
        }
    }
    __half2 p0 = __floats2half2_rn(acc.x, acc.y);
    __half2 p1 = __floats2half2_rn(acc.z, acc.w);
    uint2 u;
    u.x = *(uint32_t*)&p0;
    u.y = *(uint32_t*)&p1;
    O[(size_t)w * 32 + lane] = u;
}

// ==== classifier with fused BN/ReLU/residual A-stage: out = h3 @ W^T + b ===
#define CLS_SMEM ((2 * 128 + 2 * 40) * HST * 4 + 40 * 4)

__global__ __launch_bounds__(256)
void k_cls_bn(const float* __restrict__ Z, const uint2* __restrict__ X0,
              const float* __restrict__ W, const float* __restrict__ bias,
              float* __restrict__ O, int nrows) {
    extern __shared__ uint32_t smu[];
    uint32_t* sAh = smu;                       // [128][HST]
    uint32_t* sAl = smu + 128 * HST;
    uint32_t* sBh = smu + 2 * 128 * HST;       // [40][HST]
    uint32_t* sBl = sBh + 40 * HST;
    float* sBias = (float*)(sBl + 40 * HST);   // [40]

    const int tid = threadIdx.x;
    const int wid = tid >> 5, lane = tid & 31;
    const int rowBase = blockIdx.x * 128;
    const int r = lane >> 2, c = lane & 3;

    const float4* Z4 = (const float4*)Z;
#pragma unroll
    for (int it = 0; it < 16; ++it) {
        int vec = tid + it * 256;
        int row = vec >> 5, q = vec & 31;
        int gr = rowBase + row;
        float4 h = make_float4(0.f, 0.f, 0.f, 0.f);
        if (gr < nrows) {
            float4 z = Z4[(size_t)gr * 32 + q];
            float4 sc = ((const float4*)g_scale)[q];
            float4 sh = ((const float4*)g_shift)[q];
            h.x = fmaxf(fmaf(z.x, sc.x, sh.x), 0.f);
            h.y = fmaxf(fmaf(z.y, sc.y, sh.y), 0.f);
            h.z = fmaxf(fmaf(z.z, sc.z, sh.z), 0.f);
            h.w = fmaxf(fmaf(z.w, sc.w, sh.w), 0.f);
            uint2 u = X0[(size_t)gr * 32 + q];
            float2 x0 = __half22float2(*(__half2*)&u.x);
            float2 x1 = __half22float2(*(__half2*)&u.y);
            h.x += x0.x; h.y += x0.y; h.z += x1.x; h.w += x1.y;
        }
        uint32_t h0, l0, h1, l1;
        split_h2(h.x, h.y, h0, l0);
        split_h2(h.z, h.w, h1, l1);
        int idx = row * HST + 2 * q;
        *(uint2*)&sAh[idx] = make_uint2(h0, h1);
        *(uint2*)&sAl[idx] = make_uint2(l0, l1);
    }
    const float4* W4 = (const float4*)W;   // [40][128] -> 1280 float4
#pragma unroll
    for (int it = 0; it < 5; ++it) {
        int vec = tid + it * 256;
        int row = vec >> 5, q = vec & 31;
        float4 v = W4[vec];
        uint32_t h0, l0, h1, l1;
        split_h2(v.x, v.y, h0, l0);
        split_h2(v.z, v.w, h1, l1);
        int idx = row * HST + 2 * q;
        *(uint2*)&sBh[idx] = make_uint2(h0, h1);
        *(uint2*)&sBl[idx] = make_uint2(l0, l1);
    }
    if (tid < DOUT) sBias[tid] = bias[tid];
    __syncthreads();

    float acc[5][4];
#pragma unroll
    for (int nt = 0; nt < 5; ++nt)
#pragma unroll
        for (int i = 0; i < 4; ++i) acc[nt][i] = 0.f;

#pragma unroll 1
    for (int ks = 0; ks < 8; ++ks) {
        const int kb = ks * 8 + c;
        int ba = (wid * 16 + r) * HST + kb;
        uint32_t ah[4], al[4];
        ah[0] = sAh[ba];
        ah[1] = sAh[ba + 8 * HST];
        ah[2] = sAh[ba + 4];
        ah[3] = sAh[ba + 8 * HST + 4];
        al[0] = sAl[ba];
        al[1] = sAl[ba + 8 * HST];
        al[2] = sAl[ba + 4];
        al[3] = sAl[ba + 8 * HST + 4];
#pragma unroll
        for (int nt = 0; nt < 5; ++nt) {
            int bb = (nt * 8 + r) * HST + kb;
            uint32_t bh0 = sBh[bb], bh1 = sBh[bb + 4];
            uint32_t bl0 = sBl[bb], bl1 = sBl[bb + 4];
            mma16(acc[nt], ah, bh0, bh1);
            mma16(acc[nt], ah, bl0, bl1);
            mma16(acc[nt], al, bh0, bh1);
        }
    }

    const int R0 = rowBase + wid * 16 + r;
    const int R1 = R0 + 8;
#pragma unroll
    for (int nt = 0; nt < 5; ++nt) {
        int C0 = nt * 8 + 2 * c;
        float b0 = sBias[C0], b1 = sBias[C0 + 1];
        if (R0 < nrows)
            *(float2*)&O[(size_t)R0 * DOUT + C0] = make_float2(acc[nt][0] + b0, acc[nt][1] + b1);
        if (R1 < nrows)
            *(float2*)&O[(size_t)R1 * DOUT + C0] = make_float2(acc[nt][2] + b0, acc[nt][3] + b1);
    }
}

// ===================== driver ===============================================
extern "C" void kernel_launch(void* const* d_in, const int* in_sizes, int n_in,
                              void* d_out, int out_size) {
    const float* x      = (const float*)d_in[0];
    const int*   ei     = (const int*)d_in[1];
    const float* fc_w   = (const float*)d_in[2];
    const float* fc_b   = (const float*)d_in[3];
    const float* conv_w = (const float*)d_in[4];
    const float* conv_b = (const float*)d_in[5];
    const float* gamma  = (const float*)d_in[6];
    const float* beta   = (const float*)d_in[7];
    const float* cls_w  = (const float*)d_in[8];
    const float* cls_b  = (const float*)d_in[9];
    float* out = (float*)d_out;

    float* bB;
    __half *hH, *x0h, *aggH;
    cudaGetSymbolAddress((void**)&bB, g_bB);
    cudaGetSymbolAddress((void**)&hH, g_hH);
    cudaGetSymbolAddress((void**)&x0h, g_x0h);
    cudaGetSymbolAddress((void**)&aggH, g_aggH);

    cudaFuncSetAttribute(k_gemm_t<false>, cudaFuncAttributeMaxDynamicSharedMemorySize, GEMM_SMEM_F);
    cudaFuncSetAttribute(k_gemm_t<true>,  cudaFuncAttributeMaxDynamicSharedMemorySize, GEMM_SMEM_H);
    cudaFuncSetAttribute(k_cls_bn, cudaFuncAttributeMaxDynamicSharedMemorySize, CLS_SMEM);

    const int nodeBlocks = (NN + 255) / 256;
    const int edgeBlocks = (EE + 255) / 256;
    const int vecBlocks  = (NN * 32) / 256;     // 12500

    // graph build
    k_zero_build<<<nodeBlocks, 256>>>();
    k_degree<<<edgeBlocks, 256>>>(ei);
    k_scan_part<<<SCANB, 256>>>();
    k_scan_add2<<<SCANB, 256>>>();
    k_fill<<<edgeBlocks, 256>>>(ei);

    // layer 0: fc (BN0 prep in last GEMM block) -> relu ; x0 = h0 (fp16)
    k_gemm_t<false><<<GEMMGRID, 256, GEMM_SMEM_F>>>(x, fc_w, fc_b, bB,
                                                    gamma, beta, NN);
    k_bnfused<<<vecBlocks, 256>>>((const float4*)bB, (const uint2*)0, (uint2*)x0h, NN * 32);

    for (int i = 0; i < 3; ++i) {
        const __half* hin = (i == 0) ? x0h : hH;
        k_spmm<<<vecBlocks, 256>>>((const uint2*)hin, (uint2*)aggH);
        k_gemm_t<true><<<GEMMGRID, 256, GEMM_SMEM_H>>>(aggH, conv_w + i * DH * DH,
                                                       conv_b + i * DH, bB,
                                                       gamma + (i + 1) * DH,
                                                       beta + (i + 1) * DH, NN);
        if (i < 2)
            k_bnfused<<<vecBlocks, 256>>>((const float4*)bB, (const uint2*)x0h,
                                          (uint2*)hH, NN * 32);
    }

    // classifier with fused BN/ReLU/residual A-stage (layer-3 scale/shift)
    k_cls_bn<<<GEMMGRID, 256, CLS_SMEM>>>(bB, (const uint2*)x0h, cls_w, cls_b, out, NN);
}

// round 16
// speedup vs baseline: 1.0134x; 1.0134x over previous
#include <cuda_runtime.h>
#include <cuda_fp16.h>
#include <cstdint>

#define NN 100000
#define EE 1600000
#define DH 128
#define DOUT 40
#define BN_EPS 1e-5f
#define HST 68   // half2 stride per row in GEMM smem (4B units), conflict-free
#define SCANB 98 // (NN + 1023) / 1024

// ===================== scratch ==============================================
__device__ __half g_x0h[NN * DH];   // x0 residual, fp16 (== fp16 h0)
__device__ __half g_hH[NN * DH];    // current h for SPMM gather (fp16)
__device__ __half g_aggH[NN * DH];  // SPMM output (fp16) -> GEMM A
__device__ float  g_bB[NN * DH];    // z = GEMM output
__device__ int    g_deg[NN];
__device__ int    g_fill[NN];
__device__ float  g_dinv[NN];
__device__ int    g_rowptr[NN + 1];
__device__ int2   g_edge[EE];       // {src, float bits of val}
__device__ int    g_bsum[128];
__device__ float  g_stats[2 * DH];
__device__ float  g_scale[DH];
__device__ float  g_shift[DH];

// ===================== graph build ==========================================
__global__ void k_zero_build() {
    int i = blockIdx.x * 256 + threadIdx.x;
    if (i < NN) { g_deg[i] = 0; g_fill[i] = 0; }
}

__global__ void k_degree(const int* __restrict__ ei) {
    int e = blockIdx.x * 256 + threadIdx.x;
    if (e < EE) atomicAdd(&g_deg[ei[EE + e]], 1);
}

__global__ void k_scan_part() {
    __shared__ int ws[8];
    int t = threadIdx.x, b = blockIdx.x;
    int base = b * 1024 + t * 4;
    int4 d = make_int4(0, 0, 0, 0);
    if (base + 3 < NN) d = *(const int4*)&g_deg[base];
    else {
        if (base + 0 < NN) d.x = g_deg[base + 0];
        if (base + 1 < NN) d.y = g_deg[base + 1];
        if (base + 2 < NN) d.z = g_deg[base + 2];
    }
    float4 dv;
    dv.x = d.x > 0 ? rsqrtf((float)d.x) : 0.f;
    dv.y = d.y > 0 ? rsqrtf((float)d.y) : 0.f;
    dv.z = d.z > 0 ? rsqrtf((float)d.z) : 0.f;
    dv.w = d.w > 0 ? rsqrtf((float)d.w) : 0.f;
    if (base + 3 < NN) *(float4*)&g_dinv[base] = dv;
    else {
        if (base + 0 < NN) g_dinv[base + 0] = dv.x;
        if (base + 1 < NN) g_dinv[base + 1] = dv.y;
        if (base + 2 < NN) g_dinv[base + 2] = dv.z;
    }
    int s = d.x + d.y + d.z + d.w;
    int lane = t & 31, wid = t >> 5;
    int sc = s;
#pragma unroll
    for (int o = 1; o < 32; o <<= 1) {
        int u = __shfl_up_sync(0xffffffffu, sc, o);
        if (lane >= o) sc += u;
    }
    if (lane == 31) ws[wid] = sc;
    __syncthreads();
    if (t < 8) {
        int v = ws[t];
#pragma unroll
        for (int o = 1; o < 8; o <<= 1) {
            int u = __shfl_up_sync(0xffu, v, o);
            if (t >= o) v += u;
        }
        ws[t] = v;
    }
    __syncthreads();
    int excl = sc - s + (wid ? ws[wid - 1] : 0);
    int4 rp;
    rp.x = excl; rp.y = excl + d.x; rp.z = rp.y + d.y; rp.w = rp.z + d.z;
    if (base + 3 < NN) *(int4*)&g_rowptr[base] = rp;
    else {
        if (base + 0 < NN) g_rowptr[base + 0] = rp.x;
        if (base + 1 < NN) g_rowptr[base + 1] = rp.y;
        if (base + 2 < NN) g_rowptr[base + 2] = rp.z;
    }
    if (t == 255) g_bsum[b] = excl + s;
}

__global__ void k_scan_add2() {
    __shared__ int soff;
    int t = threadIdx.x, b = blockIdx.x;
    if (t < 32) {
        int acc = 0, tot = 0;
#pragma unroll
        for (int i = 0; i < 4; ++i) {
            int idx = i * 32 + t;
            int v = (idx < SCANB) ? g_bsum[idx] : 0;
            tot += v;
            if (idx < b) acc += v;
        }
#pragma unroll
        for (int o = 16; o; o >>= 1) {
            acc += __shfl_xor_sync(0xffffffffu, acc, o);
            tot += __shfl_xor_sync(0xffffffffu, tot, o);
        }
        if (t == 0) {
            soff = acc;
            if (b == 0) g_rowptr[NN] = tot;
        }
    }
    __syncthreads();
    int off = soff;
    if (off == 0) return;
    int base = b * 1024 + t * 4;
    if (base + 3 < NN) {
        int4 rp = *(const int4*)&g_rowptr[base];
        rp.x += off; rp.y += off; rp.z += off; rp.w += off;
        *(int4*)&g_rowptr[base] = rp;
    } else {
        for (int i = 0; i < 4; ++i)
            if (base + i < NN) g_rowptr[base + i] += off;
    }
}

__global__ void k_fill(const int* __restrict__ ei) {
    int e = blockIdx.x * 256 + threadIdx.x;
    if (e >= EE) return;
    int r = ei[e];
    int c = ei[EE + e];
    int p = g_rowptr[c] + atomicAdd(&g_fill[c], 1);
    float v = g_dinv[r] * g_dinv[c];
    g_edge[p] = make_int2(r, __float_as_int(v));
}

// ===================== split-fp16 mma.sync GEMM =============================
__device__ __forceinline__ void split_h2(float x, float y, uint32_t& hi, uint32_t& lo) {
    __half2 h = __floats2half2_rn(x, y);
    float2 hf = __half22float2(h);
    __half2 l = __floats2half2_rn(x - hf.x, y - hf.y);
    hi = *(uint32_t*)&h;
    lo = *(uint32_t*)&l;
}

__device__ __forceinline__ void mma16(float* d, const uint32_t* a, uint32_t b0, uint32_t b1) {
    asm volatile(
        "mma.sync.aligned.m16n8k16.row.col.f32.f16.f16.f32 "
        "{%0,%1,%2,%3}, {%4,%5,%6,%7}, {%8,%9}, {%0,%1,%2,%3};"
        : "+f"(d[0]), "+f"(d[1]), "+f"(d[2]), "+f"(d[3])
        : "r"(a[0]), "r"(a[1]), "r"(a[2]), "r"(a[3]), "r"(b0), "r"(b1));
}

#define GEMM_SMEM_F (4 * 128 * HST * 4 + 3 * 128 * 4)
#define GEMM_SMEM_H (3 * 128 * HST * 4 + 3 * 128 * 4)

template <bool AHALF>
__global__ __launch_bounds__(256)
void k_gemm_t(const void* __restrict__ Ain, const float* __restrict__ W,
              const float* __restrict__ bias, float* __restrict__ Z, int nrows) {
    extern __shared__ uint32_t smu[];
    uint32_t* sAh = smu;
    uint32_t* sAl = AHALF ? smu : smu + 128 * HST;
    uint32_t* sBh = smu + (AHALF ? 1 : 2) * 128 * HST;
    uint32_t* sBl = sBh + 128 * HST;
    float* sSum  = (float*)(sBl + 128 * HST);
    float* sSq   = sSum + 128;
    float* sBias = sSq + 128;

    const int tid = threadIdx.x;
    const int wid = tid >> 5, lane = tid & 31;
    const int rowBase = blockIdx.x * 128;
    const int r = lane >> 2, c = lane & 3;

    if (AHALF) {
        const uint2* A2 = (const uint2*)Ain;
#pragma unroll
        for (int it = 0; it < 16; ++it) {
            int vec = tid + it * 256;
            int row = vec >> 5, q = vec & 31;
            int gr = rowBase + row;
            uint2 u = make_uint2(0u, 0u);
            if (gr < nrows) u = A2[(size_t)gr * 32 + q];
            *(uint2*)&sAh[row * HST + 2 * q] = u;
        }
    } else {
        const float4* A4 = (const float4*)Ain;
#pragma unroll
        for (int it = 0; it < 16; ++it) {
            int vec = tid + it * 256;
            int row = vec >> 5, q = vec & 31;
            int gr = rowBase + row;
            float4 v = make_float4(0.f, 0.f, 0.f, 0.f);
            if (gr < nrows) v = A4[(size_t)gr * 32 + q];
            uint32_t h0, l0, h1, l1;
            split_h2(v.x, v.y, h0, l0);
            split_h2(v.z, v.w, h1, l1);
            int idx = row * HST + 2 * q;
            *(uint2*)&sAh[idx] = make_uint2(h0, h1);
            *(uint2*)&sAl[idx] = make_uint2(l0, l1);
        }
    }
    const float4* W4 = (const float4*)W;
#pragma unroll
    for (int it = 0; it < 16; ++it) {
        int vec = tid + it * 256;
        int row = vec >> 5, q = vec & 31;
        float4 v = W4[vec];
        uint32_t h0, l0, h1, l1;
        split_h2(v.x, v.y, h0, l0);
        split_h2(v.z, v.w, h1, l1);
        int idx = row * HST + 2 * q;
        *(uint2*)&sBh[idx] = make_uint2(h0, h1);
        *(uint2*)&sBl[idx] = make_uint2(l0, l1);
    }
    if (tid < 128) { sSum[tid] = 0.f; sSq[tid] = 0.f; sBias[tid] = bias[tid]; }
    __syncthreads();

    const int wm = wid & 3, wn = wid >> 2;
    float acc[2][8][4];
#pragma unroll
    for (int mt = 0; mt < 2; ++mt)
#pragma unroll
        for (int nt = 0; nt < 8; ++nt)
#pragma unroll
            for (int i = 0; i < 4; ++i) acc[mt][nt][i] = 0.f;

#pragma unroll 1
    for (int ks = 0; ks < 8; ++ks) {
        const int kb = ks * 8 + c;
        uint32_t ah[2][4], al[2][4];
#pragma unroll
        for (int mt = 0; mt < 2; ++mt) {
            int ba = (wm * 32 + mt * 16 + r) * HST + kb;
            ah[mt][0] = sAh[ba];
            ah[mt][1] = sAh[ba + 8 * HST];
            ah[mt][2] = sAh[ba + 4];
            ah[mt][3] = sAh[ba + 8 * HST + 4];
            if (!AHALF) {
                al[mt][0] = sAl[ba];
                al[mt][1] = sAl[ba + 8 * HST];
                al[mt][2] = sAl[ba + 4];
                al[mt][3] = sAl[ba + 8 * HST + 4];
            }
        }
#pragma unroll
        for (int nt = 0; nt < 8; ++nt) {
            int bb = (wn * 64 + nt * 8 + r) * HST + kb;
            uint32_t bh0 = sBh[bb], bh1 = sBh[bb + 4];
            uint32_t bl0 = sBl[bb], bl1 = sBl[bb + 4];
#pragma unroll
            for (int mt = 0; mt < 2; ++mt) {
                mma16(acc[mt][nt], ah[mt], bh0, bh1);
                mma16(acc[mt][nt], ah[mt], bl0, bl1);
                if (!AHALF) mma16(acc[mt][nt], al[mt], bh0, bh1);
            }
        }
    }

    float cs[16], cq[16];
#pragma unroll
    for (int i = 0; i < 16; ++i) { cs[i] = 0.f; cq[i] = 0.f; }

#pragma unroll
    for (int nt = 0; nt < 8; ++nt) {
        int C0 = wn * 64 + nt * 8 + 2 * c;
        float b0 = sBias[C0], b1 = sBias[C0 + 1];
#pragma unroll
        for (int mt = 0; mt < 2; ++mt) {
            int R0 = rowBase + wm * 32 + mt * 16 + r;
            int R1 = R0 + 8;
            if (R0 < nrows) {
                float z0 = acc[mt][nt][0] + b0;
                float z1 = acc[mt][nt][1] + b1;
                *(float2*)&Z[(size_t)R0 * 128 + C0] = make_float2(z0, z1);
                cs[2 * nt] += z0; cq[2 * nt] += z0 * z0;
                cs[2 * nt + 1] += z1; cq[2 * nt + 1] += z1 * z1;
            }
            if (R1 < nrows) {
                float z2 = acc[mt][nt][2] + b0;
                float z3 = acc[mt][nt][3] + b1;
                *(float2*)&Z[(size_t)R1 * 128 + C0] = make_float2(z2, z3);
                cs[2 * nt] += z2; cq[2 * nt] += z2 * z2;
                cs[2 * nt + 1] += z3; cq[2 * nt + 1] += z3 * z3;
            }
        }
    }
#pragma unroll
    for (int o = 4; o <= 16; o <<= 1) {
#pragma unroll
        for (int i = 0; i < 16; ++i) {
            cs[i] += __shfl_xor_sync(0xffffffffu, cs[i], o);
            cq[i] += __shfl_xor_sync(0xffffffffu, cq[i], o);
        }
    }
    if (r == 0) {
#pragma unroll
        for (int nt = 0; nt < 8; ++nt) {
            int C0 = wn * 64 + nt * 8 + 2 * c;
            atomicAdd(&sSum[C0],     cs[2 * nt]);
            atomicAdd(&sSum[C0 + 1], cs[2 * nt + 1]);
            atomicAdd(&sSq[C0],      cq[2 * nt]);
            atomicAdd(&sSq[C0 + 1],  cq[2 * nt + 1]);
        }
    }
    __syncthreads();
    if (tid < 128) {
        atomicAdd(&g_stats[tid], sSum[tid]);
        atomicAdd(&g_stats[128 + tid], sSq[tid]);
    }
}

// ========== BN prep (reads stats, then re-zeroes for next GEMM) ============
__global__ void k_bnprep(const float* __restrict__ gamma, const float* __restrict__ beta) {
    int j = threadIdx.x;
    if (j < DH) {
        float s = g_stats[j];
        float q = g_stats[128 + j];
        float mu = s * (1.0f / (float)NN);
        float var = q * (1.0f / (float)NN) - mu * mu;
        float rs = rsqrtf(var + BN_EPS);
        float sc = gamma[j] * rs;
        g_scale[j] = sc;
        g_shift[j] = beta[j] - mu * sc;
        g_stats[j] = 0.f;
        g_stats[128 + j] = 0.f;
    }
}

// ========== fused BN/ReLU/residual; fp16 residual input =====================
__global__ void k_bnfused(const float4* __restrict__ Z, const uint2* __restrict__ X0,
                          uint2* __restrict__ OutH, int nvec) {
    int i = blockIdx.x * 256 + threadIdx.x;
    if (i >= nvec) return;
    int c4 = i & 31;
    float4 sc = ((const float4*)g_scale)[c4];
    float4 sh = ((const float4*)g_shift)[c4];
    float4 z = Z[i];
    float4 h;
    h.x = fmaxf(fmaf(z.x, sc.x, sh.x), 0.f);
    h.y = fmaxf(fmaf(z.y, sc.y, sh.y), 0.f);
    h.z = fmaxf(fmaf(z.z, sc.z, sh.z), 0.f);
    h.w = fmaxf(fmaf(z.w, sc.w, sh.w), 0.f);
    if (X0) {
        uint2 u = X0[i];
        float2 x0 = __half22float2(*(__half2*)&u.x);
        float2 x1 = __half22float2(*(__half2*)&u.y);
        h.x += x0.x; h.y += x0.y; h.z += x1.x; h.w += x1.y;
    }
    __half2 p0 = __floats2half2_rn(h.x, h.y);
    __half2 p1 = __floats2half2_rn(h.z, h.w);
    uint2 u;
    u.x = *(uint32_t*)&p0;
    u.y = *(uint32_t*)&p1;
    OutH[i] = u;
}

// ===== SPMM: warp/node, shfl broadcast, fp16 gather, fp32 acc, MLP=4 =======
__device__ __forceinline__ void spmm_fma(float4& acc, float vj, uint2 u) {
    float2 f0 = __half22float2(*(__half2*)&u.x);
    float2 f1 = __half22float2(*(__half2*)&u.y);
    acc.x = fmaf(vj, f0.x, acc.x);
    acc.y = fmaf(vj, f0.y, acc.y);
    acc.z = fmaf(vj, f1.x, acc.z);
    acc.w = fmaf(vj, f1.y, acc.w);
}

__global__ void k_spmm(const uint2* __restrict__ H, uint2* __restrict__ O) {
    int gt = blockIdx.x * 256 + threadIdx.x;
    int w = gt >> 5;
    int lane = gt & 31;
    if (w >= NN) return;
    int rp0 = g_rowptr[w], rp1 = g_rowptr[w + 1];
    float4 acc = make_float4(0.f, 0.f, 0.f, 0.f);
    for (int base = rp0; base < rp1; base += 32) {
        int nb = min(32, rp1 - base);
        int s = 0; float v = 0.f;
        if (lane < nb) {
            int2 e = g_edge[base + lane];
            s = e.x; v = __int_as_float(e.y);
        }
        int j = 0;
#pragma unroll 1
        for (; j + 4 <= nb; j += 4) {
            int s0 = __shfl_sync(0xffffffffu, s, j);
            int s1 = __shfl_sync(0xffffffffu, s, j + 1);
            int s2 = __shfl_sync(0xffffffffu, s, j + 2);
            int s3 = __shfl_sync(0xffffffffu, s, j + 3);
            float v0 = __shfl_sync(0xffffffffu, v, j);
            float v1 = __shfl_sync(0xffffffffu, v, j + 1);
            float v2 = __shfl_sync(0xffffffffu, v, j + 2);
            float v3 = __shfl_sync(0xffffffffu, v, j + 3);
            uint2 u0 = H[(size_t)s0 * 32 + lane];
            uint2 u1 = H[(size_t)s1 * 32 + lane];
            uint2 u2 = H[(size_t)s2 * 32 + lane];
            uint2 u3 = H[(size_t)s3 * 32 + lane];
            spmm_fma(acc, v0, u0);
            spmm_fma(acc, v1, u1);
            spmm_fma(acc, v2, u2);
            spmm_fma(acc, v3, u3);
        }
        for (; j < nb; ++j) {
            int sj = __shfl_sync(0xffffffffu, s, j);
            float vj = __shfl_sync(0xffffffffu, v, j);
            spmm_fma(acc, vj, H[(size_t)sj * 32 + lane]);
        }
    }
    __half2 p0 = __floats2half2_rn(acc.x, acc.y);
    __half2 p1 = __floats2half2_rn(acc.z, acc.w);
    uint2 u;
    u.x = *(uint32_t*)&p0;
    u.y = *(uint32_t*)&p1;
    O[(size_t)w * 32 + lane] = u;
}

// ==== classifier with fused BN/ReLU/residual A-stage: out = h3 @ W^T + b ===
// h3 = relu(z*scale+shift) + x0 computed inline (identical math to k_bnfused)
#define CLS_SMEM ((2 * 128 + 2 * 40) * HST * 4 + 40 * 4)

__global__ __launch_bounds__(256)
void k_cls_bn(const float* __restrict__ Z, const uint2* __restrict__ X0,
              const float* __restrict__ W, const float* __restrict__ bias,
              float* __restrict__ O, int nrows) {
    extern __shared__ uint32_t smu[];
    uint32_t* sAh = smu;                       // [128][HST]
    uint32_t* sAl = smu + 128 * HST;
    uint32_t* sBh = smu + 2 * 128 * HST;       // [40][HST]
    uint32_t* sBl = sBh + 40 * HST;
    float* sBias = (float*)(sBl + 40 * HST);   // [40]

    const int tid = threadIdx.x;
    const int wid = tid >> 5, lane = tid & 31;
    const int rowBase = blockIdx.x * 128;
    const int r = lane >> 2, c = lane & 3;

    const float4* Z4 = (const float4*)Z;
#pragma unroll
    for (int it = 0; it < 16; ++it) {
        int vec = tid + it * 256;
        int row = vec >> 5, q = vec & 31;
        int gr = rowBase + row;
        float4 h = make_float4(0.f, 0.f, 0.f, 0.f);
        if (gr < nrows) {
            float4 z = Z4[(size_t)gr * 32 + q];
            float4 sc = ((const float4*)g_scale)[q];
            float4 sh = ((const float4*)g_shift)[q];
            h.x = fmaxf(fmaf(z.x, sc.x, sh.x), 0.f);
            h.y = fmaxf(fmaf(z.y, sc.y, sh.y), 0.f);
            h.z = fmaxf(fmaf(z.z, sc.z, sh.z), 0.f);
            h.w = fmaxf(fmaf(z.w, sc.w, sh.w), 0.f);
            uint2 u = X0[(size_t)gr * 32 + q];
            float2 x0 = __half22float2(*(__half2*)&u.x);
            float2 x1 = __half22float2(*(__half2*)&u.y);
            h.x += x0.x; h.y += x0.y; h.z += x1.x; h.w += x1.y;
        }
        uint32_t h0, l0, h1, l1;
        split_h2(h.x, h.y, h0, l0);
        split_h2(h.z, h.w, h1, l1);
        int idx = row * HST + 2 * q;
        *(uint2*)&sAh[idx] = make_uint2(h0, h1);
        *(uint2*)&sAl[idx] = make_uint2(l0, l1);
    }
    const float4* W4 = (const float4*)W;   // [40][128] -> 1280 float4
#pragma unroll
    for (int it = 0; it < 5; ++it) {
        int vec = tid + it * 256;
        int row = vec >> 5, q = vec & 31;
        float4 v = W4[vec];
        uint32_t h0, l0, h1, l1;
        split_h2(v.x, v.y, h0, l0);
        split_h2(v.z, v.w, h1, l1);
        int idx = row * HST + 2 * q;
        *(uint2*)&sBh[idx] = make_uint2(h0, h1);
        *(uint2*)&sBl[idx] = make_uint2(l0, l1);
    }
    if (tid < DOUT) sBias[tid] = bias[tid];
    __syncthreads();

    float acc[5][4];
#pragma unroll
    for (int nt = 0; nt < 5; ++nt)
#pragma unroll
        for (int i = 0; i < 4; ++i) acc[nt][i] = 0.f;

#pragma unroll 1
    for (int ks = 0; ks < 8; ++ks) {
        const int kb = ks * 8 + c;
        int ba = (wid * 16 + r) * HST + kb;
        uint32_t ah[4], al[4];
        ah[0] = sAh[ba];
        ah[1] = sAh[ba + 8 * HST];
        ah[2] = sAh[ba + 4];
        ah[3] = sAh[ba + 8 * HST + 4];
        al[0] = sAl[ba];
        al[1] = sAl[ba + 8 * HST];
        al[2] = sAl[ba + 4];
        al[3] = sAl[ba + 8 * HST + 4];
#pragma unroll
        for (int nt = 0; nt < 5; ++nt) {
            int bb = (nt * 8 + r) * HST + kb;
            uint32_t bh0 = sBh[bb], bh1 = sBh[bb + 4];
            uint32_t bl0 = sBl[bb], bl1 = sBl[bb + 4];
            mma16(acc[nt], ah, bh0, bh1);
            mma16(acc[nt], ah, bl0, bl1);
            mma16(acc[nt], al, bh0, bh1);
        }
    }

    const int R0 = rowBase + wid * 16 + r;
    const int R1 = R0 + 8;
#pragma unroll
    for (int nt = 0; nt < 5; ++nt) {
        int C0 = nt * 8 + 2 * c;
        float b0 = sBias[C0], b1 = sBias[C0 + 1];
        if (R0 < nrows)
            *(float2*)&O[(size_t)R0 * DOUT + C0] = make_float2(acc[nt][0] + b0, acc[nt][1] + b1);
        if (R1 < nrows)
            *(float2*)&O[(size_t)R1 * DOUT + C0] = make_float2(acc[nt][2] + b0, acc[nt][3] + b1);
    }
}

// ===================== driver ===============================================
extern "C" void kernel_launch(void* const* d_in, const int* in_sizes, int n_in,
                              void* d_out, int out_size) {
    const float* x      = (const float*)d_in[0];
    const int*   ei     = (const int*)d_in[1];
    const float* fc_w   = (const float*)d_in[2];
    const float* fc_b   = (const float*)d_in[3];
    const float* conv_w = (const float*)d_in[4];
    const float* conv_b = (const float*)d_in[5];
    const float* gamma  = (const float*)d_in[6];
    const float* beta   = (const float*)d_in[7];
    const float* cls_w  = (const float*)d_in[8];
    const float* cls_b  = (const float*)d_in[9];
    float* out = (float*)d_out;

    float* bB;
    __half *hH, *x0h, *aggH;
    cudaGetSymbolAddress((void**)&bB, g_bB);
    cudaGetSymbolAddress((void**)&hH, g_hH);
    cudaGetSymbolAddress((void**)&x0h, g_x0h);
    cudaGetSymbolAddress((void**)&aggH, g_aggH);

    cudaFuncSetAttribute(k_gemm_t<false>, cudaFuncAttributeMaxDynamicSharedMemorySize, GEMM_SMEM_F);
    cudaFuncSetAttribute(k_gemm_t<true>,  cudaFuncAttributeMaxDynamicSharedMemorySize, GEMM_SMEM_H);
    cudaFuncSetAttribute(k_cls_bn, cudaFuncAttributeMaxDynamicSharedMemorySize, CLS_SMEM);

    const int nodeBlocks = (NN + 255) / 256;
    const int edgeBlocks = (EE + 255) / 256;
    const int gemmGrid   = (NN + 127) / 128;    // 782
    const int vecBlocks  = (NN * 32) / 256;     // 12500

    // graph build
    k_zero_build<<<nodeBlocks, 256>>>();
    k_degree<<<edgeBlocks, 256>>>(ei);
    k_scan_part<<<SCANB, 256>>>();
    k_scan_add2<<<SCANB, 256>>>();
    k_fill<<<edgeBlocks, 256>>>(ei);

    // layer 0: fc -> bn0 -> relu ; x0 (fp16) doubles as h0 for SPMM1
    k_gemm_t<false><<<gemmGrid, 256, GEMM_SMEM_F>>>(x, fc_w, fc_b, bB, NN);
    k_bnprep<<<1, 128>>>(gamma, beta);
    k_bnfused<<<vecBlocks, 256>>>((const float4*)bB, (const uint2*)0, (uint2*)x0h, NN * 32);

    for (int i = 0; i < 3; ++i) {
        const __half* hin = (i == 0) ? x0h : hH;
        k_spmm<<<vecBlocks, 256>>>((const uint2*)hin, (uint2*)aggH);
        k_gemm_t<true><<<gemmGrid, 256, GEMM_SMEM_H>>>(aggH, conv_w + i * DH * DH,
                                                       conv_b + i * DH, bB, NN);
        k_bnprep<<<1, 128>>>(gamma + (i + 1) * DH, beta + (i + 1) * DH);
        if (i < 2)
            k_bnfused<<<vecBlocks, 256>>>((const float4*)bB, (const uint2*)x0h,
                                          (uint2*)hH, NN * 32);
    }

    // classifier with fused BN/ReLU/residual A-stage (uses layer-3 scale/shift)
    k_cls_bn<<<gemmGrid, 256, CLS_SMEM>>>(bB, (const uint2*)x0h, cls_w, cls_b, out, NN);
}

// round 17
// speedup vs baseline: 1.0229x; 1.0094x over previous
#include <cuda_runtime.h>
#include <cuda_fp16.h>
#include <cstdint>

#define NN 100000
#define EE 1600000
#define DH 128
#define DOUT 40
#define BN_EPS 1e-5f
#define HST 68   // half2 stride per row in GEMM smem (4B units), conflict-free
#define SCANB 98 // (NN + 1023) / 1024 ; <= 148 SMs -> single wave, spin-safe

// ===================== scratch ==============================================
__device__ __half g_x0h[NN * DH];   // x0 residual, fp16 (== fp16 h0)
__device__ __half g_hH[NN * DH];    // current h for SPMM gather (fp16)
__device__ __half g_aggH[NN * DH];  // SPMM output (fp16) -> GEMM A
__device__ float  g_bB[NN * DH];    // z = GEMM output
__device__ int    g_deg[NN];        // zeroed by scan tail (load-time zero on replay 0)
__device__ int    g_fill[NN];       // zeroed by scan tail
__device__ float  g_dinv[NN];
__device__ int    g_rowptr[NN + 1];
__device__ int2   g_edge[EE];       // {src, float bits of val}
__device__ int    g_bsum[128];
__device__ float  g_stats[2 * DH];
__device__ float  g_scale[DH];
__device__ float  g_shift[DH];
__device__ int    g_c1;             // scan arrival counter (self-resetting)
__device__ int    g_c2;             // scan departure counter (self-resetting)

// ===================== graph build ==========================================
__global__ void k_degree(const int* __restrict__ ei) {
    int e = blockIdx.x * 256 + threadIdx.x;
    if (e < EE) atomicAdd(&g_deg[ei[EE + e]], 1);
}

// fused scan: per-block prefix + dinv -> grid sync (98 resident blocks) ->
// offset + final rowptr write; tail re-zeroes deg/fill for the next replay.
__global__ void k_scan_fused() {
    __shared__ int ws[8];
    __shared__ int soff;
    int t = threadIdx.x, b = blockIdx.x;
    int base = b * 1024 + t * 4;

    int4 d = make_int4(0, 0, 0, 0);
    if (base + 3 < NN) d = *(const int4*)&g_deg[base];
    else {
        if (base + 0 < NN) d.x = g_deg[base + 0];
        if (base + 1 < NN) d.y = g_deg[base + 1];
        if (base + 2 < NN) d.z = g_deg[base + 2];
    }
    float4 dv;
    dv.x = d.x > 0 ? rsqrtf((float)d.x) : 0.f;
    dv.y = d.y > 0 ? rsqrtf((float)d.y) : 0.f;
    dv.z = d.z > 0 ? rsqrtf((float)d.z) : 0.f;
    dv.w = d.w > 0 ? rsqrtf((float)d.w) : 0.f;
    if (base + 3 < NN) *(float4*)&g_dinv[base] = dv;
    else {
        if (base + 0 < NN) g_dinv[base + 0] = dv.x;
        if (base + 1 < NN) g_dinv[base + 1] = dv.y;
        if (base + 2 < NN) g_dinv[base + 2] = dv.z;
    }

    int s = d.x + d.y + d.z + d.w;
    int lane = t & 31, wid = t >> 5;
    int sc = s;
#pragma unroll
    for (int o = 1; o < 32; o <<= 1) {
        int u = __shfl_up_sync(0xffffffffu, sc, o);
        if (lane >= o) sc += u;
    }
    if (lane == 31) ws[wid] = sc;
    __syncthreads();
    if (t < 8) {
        int v = ws[t];
#pragma unroll
        for (int o = 1; o < 8; o <<= 1) {
            int u = __shfl_up_sync(0xffu, v, o);
            if (t >= o) v += u;
        }
        ws[t] = v;
    }
    __syncthreads();
    int excl = sc - s + (wid ? ws[wid - 1] : 0);

    // publish block total, then wait for all 98 blocks (all resident: 98<148)
    if (t == 0) {
        g_bsum[b] = ws[7];
        __threadfence();
        atomicAdd(&g_c1, 1);
        while (atomicAdd(&g_c1, 0) < SCANB) { }
        __threadfence();
    }
    __syncthreads();

    // offset for this block + grand total
    if (t < 32) {
        int acc = 0, tot = 0;
#pragma unroll
        for (int i = 0; i < 4; ++i) {
            int idx = i * 32 + t;
            int v = (idx < SCANB) ? g_bsum[idx] : 0;
            tot += v;
            if (idx < b) acc += v;
        }
#pragma unroll
        for (int o = 16; o; o >>= 1) {
            acc += __shfl_xor_sync(0xffffffffu, acc, o);
            tot += __shfl_xor_sync(0xffffffffu, tot, o);
        }
        if (t == 0) {
            soff = acc;
            if (b == 0) g_rowptr[NN] = tot;
        }
    }
    __syncthreads();
    int off = soff;

    int4 rp;
    rp.x = off + excl; rp.y = rp.x + d.x; rp.z = rp.y + d.y; rp.w = rp.z + d.z;
    const int4 z4 = make_int4(0, 0, 0, 0);
    if (base + 3 < NN) {
        *(int4*)&g_rowptr[base] = rp;
        *(int4*)&g_deg[base]  = z4;   // rezero for next replay
        *(int4*)&g_fill[base] = z4;   // fill consumed next by k_fill (starts at 0)
    } else {
        if (base + 0 < NN) { g_rowptr[base + 0] = rp.x; g_deg[base + 0] = 0; g_fill[base + 0] = 0; }
        if (base + 1 < NN) { g_rowptr[base + 1] = rp.y; g_deg[base + 1] = 0; g_fill[base + 1] = 0; }
        if (base + 2 < NN) { g_rowptr[base + 2] = rp.z; g_deg[base + 2] = 0; g_fill[base + 2] = 0; }
    }

    // self-reset counters: last departing block resets both
    if (t == 0) {
        int old = atomicAdd(&g_c2, 1);
        if (old == SCANB - 1) { g_c1 = 0; g_c2 = 0; }
    }
}

__global__ void k_fill(const int* __restrict__ ei) {
    int e = blockIdx.x * 256 + threadIdx.x;
    if (e >= EE) return;
    int r = ei[e];
    int c = ei[EE + e];
    int p = g_rowptr[c] + atomicAdd(&g_fill[c], 1);
    float v = g_dinv[r] * g_dinv[c];
    g_edge[p] = make_int2(r, __float_as_int(v));
}

// ===================== split-fp16 mma.sync GEMM =============================
__device__ __forceinline__ void split_h2(float x, float y, uint32_t& hi, uint32_t& lo) {
    __half2 h = __floats2half2_rn(x, y);
    float2 hf = __half22float2(h);
    __half2 l = __floats2half2_rn(x - hf.x, y - hf.y);
    hi = *(uint32_t*)&h;
    lo = *(uint32_t*)&l;
}

__device__ __forceinline__ void mma16(float* d, const uint32_t* a, uint32_t b0, uint32_t b1) {
    asm volatile(
        "mma.sync.aligned.m16n8k16.row.col.f32.f16.f16.f32 "
        "{%0,%1,%2,%3}, {%4,%5,%6,%7}, {%8,%9}, {%0,%1,%2,%3};"
        : "+f"(d[0]), "+f"(d[1]), "+f"(d[2]), "+f"(d[3])
        : "r"(a[0]), "r"(a[1]), "r"(a[2]), "r"(a[3]), "r"(b0), "r"(b1));
}

#define GEMM_SMEM_F (4 * 128 * HST * 4 + 3 * 128 * 4)
#define GEMM_SMEM_H (3 * 128 * HST * 4 + 3 * 128 * 4)

template <bool AHALF>
__global__ __launch_bounds__(256)
void k_gemm_t(const void* __restrict__ Ain, const float* __restrict__ W,
              const float* __restrict__ bias, float* __restrict__ Z, int nrows) {
    extern __shared__ uint32_t smu[];
    uint32_t* sAh = smu;
    uint32_t* sAl = AHALF ? smu : smu + 128 * HST;
    uint32_t* sBh = smu + (AHALF ? 1 : 2) * 128 * HST;
    uint32_t* sBl = sBh + 128 * HST;
    float* sSum  = (float*)(sBl + 128 * HST);
    float* sSq   = sSum + 128;
    float* sBias = sSq + 128;

    const int tid = threadIdx.x;
    const int wid = tid >> 5, lane = tid & 31;
    const int rowBase = blockIdx.x * 128;
    const int r = lane >> 2, c = lane & 3;

    if (AHALF) {
        const uint2* A2 = (const uint2*)Ain;
#pragma unroll
        for (int it = 0; it < 16; ++it) {
            int vec = tid + it * 256;
            int row = vec >> 5, q = vec & 31;
            int gr = rowBase + row;
            uint2 u = make_uint2(0u, 0u);
            if (gr < nrows) u = A2[(size_t)gr * 32 + q];
            *(uint2*)&sAh[row * HST + 2 * q] = u;
        }
    } else {
        const float4* A4 = (const float4*)Ain;
#pragma unroll
        for (int it = 0; it < 16; ++it) {
            int vec = tid + it * 256;
            int row = vec >> 5, q = vec & 31;
            int gr = rowBase + row;
            float4 v = make_float4(0.f, 0.f, 0.f, 0.f);
            if (gr < nrows) v = A4[(size_t)gr * 32 + q];
            uint32_t h0, l0, h1, l1;
            split_h2(v.x, v.y, h0, l0);
            split_h2(v.z, v.w, h1, l1);
            int idx = row * HST + 2 * q;
            *(uint2*)&sAh[idx] = make_uint2(h0, h1);
            *(uint2*)&sAl[idx] = make_uint2(l0, l1);
        }
    }
    const float4* W4 = (const float4*)W;
#pragma unroll
    for (int it = 0; it < 16; ++it) {
        int vec = tid + it * 256;
        int row = vec >> 5, q = vec & 31;
        float4 v = W4[vec];
        uint32_t h0, l0, h1, l1;
        split_h2(v.x, v.y, h0, l0);
        split_h2(v.z, v.w, h1, l1);
        int idx = row * HST + 2 * q;
        *(uint2*)&sBh[idx] = make_uint2(h0, h1);
        *(uint2*)&sBl[idx] = make_uint2(l0, l1);
    }
    if (tid < 128) { sSum[tid] = 0.f; sSq[tid] = 0.f; sBias[tid] = bias[tid]; }
    __syncthreads();

    const int wm = wid & 3, wn = wid >> 2;
    float acc[2][8][4];
#pragma unroll
    for (int mt = 0; mt < 2; ++mt)
#pragma unroll
        for (int nt = 0; nt < 8; ++nt)
#pragma unroll
            for (int i = 0; i < 4; ++i) acc[mt][nt][i] = 0.f;

#pragma unroll 1
    for (int ks = 0; ks < 8; ++ks) {
        const int kb = ks * 8 + c;
        uint32_t ah[2][4], al[2][4];
#pragma unroll
        for (int mt = 0; mt < 2; ++mt) {
            int ba = (wm * 32 + mt * 16 + r) * HST + kb;
            ah[mt][0] = sAh[ba];
            ah[mt][1] = sAh[ba + 8 * HST];
            ah[mt][2] = sAh[ba + 4];
            ah[mt][3] = sAh[ba + 8 * HST + 4];
            if (!AHALF) {
                al[mt][0] = sAl[ba];
                al[mt][1] = sAl[ba + 8 * HST];
                al[mt][2] = sAl[ba + 4];
                al[mt][3] = sAl[ba + 8 * HST + 4];
            }
        }
#pragma unroll
        for (int nt = 0; nt < 8; ++nt) {
            int bb = (wn * 64 + nt * 8 + r) * HST + kb;
            uint32_t bh0 = sBh[bb], bh1 = sBh[bb + 4];
            uint32_t bl0 = sBl[bb], bl1 = sBl[bb + 4];
#pragma unroll
            for (int mt = 0; mt < 2; ++mt) {
                mma16(acc[mt][nt], ah[mt], bh0, bh1);
                mma16(acc[mt][nt], ah[mt], bl0, bl1);
                if (!AHALF) mma16(acc[mt][nt], al[mt], bh0, bh1);
            }
        }
    }

    float cs[16], cq[16];
#pragma unroll
    for (int i = 0; i < 16; ++i) { cs[i] = 0.f; cq[i] = 0.f; }

#pragma unroll
    for (int nt = 0; nt < 8; ++nt) {
        int C0 = wn * 64 + nt * 8 + 2 * c;
        float b0 = sBias[C0], b1 = sBias[C0 + 1];
#pragma unroll
        for (int mt = 0; mt < 2; ++mt) {
            int R0 = rowBase + wm * 32 + mt * 16 + r;
            int R1 = R0 + 8;
            if (R0 < nrows) {
                float z0 = acc[mt][nt][0] + b0;
                float z1 = acc[mt][nt][1] + b1;
                *(float2*)&Z[(size_t)R0 * 128 + C0] = make_float2(z0, z1);
                cs[2 * nt] += z0; cq[2 * nt] += z0 * z0;
                cs[2 * nt + 1] += z1; cq[2 * nt + 1] += z1 * z1;
            }
            if (R1 < nrows) {
                float z2 = acc[mt][nt][2] + b0;
                float z3 = acc[mt][nt][3] + b1;
                *(float2*)&Z[(size_t)R1 * 128 + C0] = make_float2(z2, z3);
                cs[2 * nt] += z2; cq[2 * nt] += z2 * z2;
                cs[2 * nt + 1] += z3; cq[2 * nt + 1] += z3 * z3;
            }
        }
    }
#pragma unroll
    for (int o = 4; o <= 16; o <<= 1) {
#pragma unroll
        for (int i = 0; i < 16; ++i) {
            cs[i] += __shfl_xor_sync(0xffffffffu, cs[i], o);
            cq[i] += __shfl_xor_sync(0xffffffffu, cq[i], o);
        }
    }
    if (r == 0) {
#pragma unroll
        for (int nt = 0; nt < 8; ++nt) {
            int C0 = wn * 64 + nt * 8 + 2 * c;
            atomicAdd(&sSum[C0],     cs[2 * nt]);
            atomicAdd(&sSum[C0 + 1], cs[2 * nt + 1]);
            atomicAdd(&sSq[C0],      cq[2 * nt]);
            atomicAdd(&sSq[C0 + 1],  cq[2 * nt + 1]);
        }
    }
    __syncthreads();
    if (tid < 128) {
        atomicAdd(&g_stats[tid], sSum[tid]);
        atomicAdd(&g_stats[128 + tid], sSq[tid]);
    }
}

// ========== BN prep (reads stats, then re-zeroes for next GEMM) ============
__global__ void k_bnprep(const float* __restrict__ gamma, const float* __restrict__ beta) {
    int j = threadIdx.x;
    if (j < DH) {
        float s = g_stats[j];
        float q = g_stats[128 + j];
        float mu = s * (1.0f / (float)NN);
        float var = q * (1.0f / (float)NN) - mu * mu;
        float rs = rsqrtf(var + BN_EPS);
        float sc = gamma[j] * rs;
        g_scale[j] = sc;
        g_shift[j] = beta[j] - mu * sc;
        g_stats[j] = 0.f;
        g_stats[128 + j] = 0.f;
    }
}

// ========== fused BN/ReLU/residual; fp16 residual input =====================
__global__ void k_bnfused(const float4* __restrict__ Z, const uint2* __restrict__ X0,
                          uint2* __restrict__ OutH, int nvec) {
    int i = blockIdx.x * 256 + threadIdx.x;
    if (i >= nvec) return;
    int c4 = i & 31;
    float4 sc = ((const float4*)g_scale)[c4];
    float4 sh = ((const float4*)g_shift)[c4];
    float4 z = Z[i];
    float4 h;
    h.x = fmaxf(fmaf(z.x, sc.x, sh.x), 0.f);
    h.y = fmaxf(fmaf(z.y, sc.y, sh.y), 0.f);
    h.z = fmaxf(fmaf(z.z, sc.z, sh.z), 0.f);
    h.w = fmaxf(fmaf(z.w, sc.w, sh.w), 0.f);
    if (X0) {
        uint2 u = X0[i];
        float2 x0 = __half22float2(*(__half2*)&u.x);
        float2 x1 = __half22float2(*(__half2*)&u.y);
        h.x += x0.x; h.y += x0.y; h.z += x1.x; h.w += x1.y;
    }
    __half2 p0 = __floats2half2_rn(h.x, h.y);
    __half2 p1 = __floats2half2_rn(h.z, h.w);
    uint2 u;
    u.x = *(uint32_t*)&p0;
    u.y = *(uint32_t*)&p1;
    OutH[i] = u;
}

// ===== SPMM: warp/node, shfl broadcast, fp16 gather, fp32 acc, MLP=4 =======
__device__ __forceinline__ void spmm_fma(float4& acc, float vj, uint2 u) {
    float2 f0 = __half22float2(*(__half2*)&u.x);
    float2 f1 = __half22float2(*(__half2*)&u.y);
    acc.x = fmaf(vj, f0.x, acc.x);
    acc.y = fmaf(vj, f0.y, acc.y);
    acc.z = fmaf(vj, f1.x, acc.z);
    acc.w = fmaf(vj, f1.y, acc.w);
}

__global__ void k_spmm(const uint2* __restrict__ H, uint2* __restrict__ O) {
    int gt = blockIdx.x * 256 + threadIdx.x;
    int w = gt >> 5;
    int lane = gt & 31;
    if (w >= NN) return;
    int rp0 = g_rowptr[w], rp1 = g_rowptr[w + 1];
    float4 acc = make_float4(0.f, 0.f, 0.f, 0.f);
    for (int base = rp0; base < rp1; base += 32) {
        int nb = min(32, rp1 - base);
        int s = 0; float v = 0.f;
        if (lane < nb) {
            int2 e = g_edge[base + lane];
            s = e.x; v = __int_as_float(e.y);
        }
        int j = 0;
#pragma unroll 1
        for (; j + 4 <= nb; j += 4) {
            int s0 = __shfl_sync(0xffffffffu, s, j);
            int s1 = __shfl_sync(0xffffffffu, s, j + 1);
            int s2 = __shfl_sync(0xffffffffu, s, j + 2);
            int s3 = __shfl_sync(0xffffffffu, s, j + 3);
            float v0 = __shfl_sync(0xffffffffu, v, j);
            float v1 = __shfl_sync(0xffffffffu, v, j + 1);
            float v2 = __shfl_sync(0xffffffffu, v, j + 2);
            float v3 = __shfl_sync(0xffffffffu, v, j + 3);
            uint2 u0 = H[(size_t)s0 * 32 + lane];
            uint2 u1 = H[(size_t)s1 * 32 + lane];
            uint2 u2 = H[(size_t)s2 * 32 + lane];
            uint2 u3 = H[(size_t)s3 * 32 + lane];
            spmm_fma(acc, v0, u0);
            spmm_fma(acc, v1, u1);
            spmm_fma(acc, v2, u2);
            spmm_fma(acc, v3, u3);
        }
        for (; j < nb; ++j) {
            int sj = __shfl_sync(0xffffffffu, s, j);
            float vj = __shfl_sync(0xffffffffu, v, j);
            spmm_fma(acc, vj, H[(size_t)sj * 32 + lane]);
        }
    }
    __half2 p0 = __floats2half2_rn(acc.x, acc.y);
    __half2 p1 = __floats2half2_rn(acc.z, acc.w);
    uint2 u;
    u.x = *(uint32_t*)&p0;
    u.y = *(uint32_t*)&p1;
    O[(size_t)w * 32 + lane] = u;
}

// ==== classifier with fused BN/ReLU/residual A-stage: out = h3 @ W^T + b ===
#define CLS_SMEM ((2 * 128 + 2 * 40) * HST * 4 + 40 * 4)

__global__ __launch_bounds__(256)
void k_cls_bn(const float* __restrict__ Z, const uint2* __restrict__ X0,
              const float* __restrict__ W, const float* __restrict__ bias,
              float* __restrict__ O, int nrows) {
    extern __shared__ uint32_t smu[];
    uint32_t* sAh = smu;                       // [128][HST]
    uint32_t* sAl = smu + 128 * HST;
    uint32_t* sBh = smu + 2 * 128 * HST;       // [40][HST]
    uint32_t* sBl = sBh + 40 * HST;
    float* sBias = (float*)(sBl + 40 * HST);   // [40]

    const int tid = threadIdx.x;
    const int wid = tid >> 5, lane = tid & 31;
    const int rowBase = blockIdx.x * 128;
    const int r = lane >> 2, c = lane & 3;

    const float4* Z4 = (const float4*)Z;
#pragma unroll
    for (int it = 0; it < 16; ++it) {
        int vec = tid + it * 256;
        int row = vec >> 5, q = vec & 31;
        int gr = rowBase + row;
        float4 h = make_float4(0.f, 0.f, 0.f, 0.f);
        if (gr < nrows) {
            float4 z = Z4[(size_t)gr * 32 + q];
            float4 sc = ((const float4*)g_scale)[q];
            float4 sh = ((const float4*)g_shift)[q];
            h.x = fmaxf(fmaf(z.x, sc.x, sh.x), 0.f);
            h.y = fmaxf(fmaf(z.y, sc.y, sh.y), 0.f);
            h.z = fmaxf(fmaf(z.z, sc.z, sh.z), 0.f);
            h.w = fmaxf(fmaf(z.w, sc.w, sh.w), 0.f);
            uint2 u = X0[(size_t)gr * 32 + q];
            float2 x0 = __half22float2(*(__half2*)&u.x);
            float2 x1 = __half22float2(*(__half2*)&u.y);
            h.x += x0.x; h.y += x0.y; h.z += x1.x; h.w += x1.y;
        }
        uint32_t h0, l0, h1, l1;
        split_h2(h.x, h.y, h0, l0);
        split_h2(h.z, h.w, h1, l1);
        int idx = row * HST + 2 * q;
        *(uint2*)&sAh[idx] = make_uint2(h0, h1);
        *(uint2*)&sAl[idx] = make_uint2(l0, l1);
    }
    const float4* W4 = (const float4*)W;   // [40][128] -> 1280 float4
#pragma unroll
    for (int it = 0; it < 5; ++it) {
        int vec = tid + it * 256;
        int row = vec >> 5, q = vec & 31;
        float4 v = W4[vec];
        uint32_t h0, l0, h1, l1;
        split_h2(v.x, v.y, h0, l0);
        split_h2(v.z, v.w, h1, l1);
        int idx = row * HST + 2 * q;
        *(uint2*)&sBh[idx] = make_uint2(h0, h1);
        *(uint2*)&sBl[idx] = make_uint2(l0, l1);
    }
    if (tid < DOUT) sBias[tid] = bias[tid];
    __syncthreads();

    float acc[5][4];
#pragma unroll
    for (int nt = 0; nt < 5; ++nt)
#pragma unroll
        for (int i = 0; i < 4; ++i) acc[nt][i] = 0.f;

#pragma unroll 1
    for (int ks = 0; ks < 8; ++ks) {
        const int kb = ks * 8 + c;
        int ba = (wid * 16 + r) * HST + kb;
        uint32_t ah[4], al[4];
        ah[0] = sAh[ba];
        ah[1] = sAh[ba + 8 * HST];
        ah[2] = sAh[ba + 4];
        ah[3] = sAh[ba + 8 * HST + 4];
        al[0] = sAl[ba];
        al[1] = sAl[ba + 8 * HST];
        al[2] = sAl[ba + 4];
        al[3] = sAl[ba + 8 * HST + 4];
#pragma unroll
        for (int nt = 0; nt < 5; ++nt) {
            int bb = (nt * 8 + r) * HST + kb;
            uint32_t bh0 = sBh[bb], bh1 = sBh[bb + 4];
            uint32_t bl0 = sBl[bb], bl1 = sBl[bb + 4];
            mma16(acc[nt], ah, bh0, bh1);
            mma16(acc[nt], ah, bl0, bl1);
            mma16(acc[nt], al, bh0, bh1);
        }
    }

    const int R0 = rowBase + wid * 16 + r;
    const int R1 = R0 + 8;
#pragma unroll
    for (int nt = 0; nt < 5; ++nt) {
        int C0 = nt * 8 + 2 * c;
        float b0 = sBias[C0], b1 = sBias[C0 + 1];
        if (R0 < nrows)
            *(float2*)&O[(size_t)R0 * DOUT + C0] = make_float2(acc[nt][0] + b0, acc[nt][1] + b1);
        if (R1 < nrows)
            *(float2*)&O[(size_t)R1 * DOUT + C0] = make_float2(acc[nt][2] + b0, acc[nt][3] + b1);
    }
}

// ===================== driver ===============================================
extern "C" void kernel_launch(void* const* d_in, const int* in_sizes, int n_in,
                              void* d_out, int out_size) {
    const float* x      = (const float*)d_in[0];
    const int*   ei     = (const int*)d_in[1];
    const float* fc_w   = (const float*)d_in[2];
    const float* fc_b   = (const float*)d_in[3];
    const float* conv_w = (const float*)d_in[4];
    const float* conv_b = (const float*)d_in[5];
    const float* gamma  = (const float*)d_in[6];
    const float* beta   = (const float*)d_in[7];
    const float* cls_w  = (const float*)d_in[8];
    const float* cls_b  = (const float*)d_in[9];
    float* out = (float*)d_out;

    float* bB;
    __half *hH, *x0h, *aggH;
    cudaGetSymbolAddress((void**)&bB, g_bB);
    cudaGetSymbolAddress((void**)&hH, g_hH);
    cudaGetSymbolAddress((void**)&x0h, g_x0h);
    cudaGetSymbolAddress((void**)&aggH, g_aggH);

    cudaFuncSetAttribute(k_gemm_t<false>, cudaFuncAttributeMaxDynamicSharedMemorySize, GEMM_SMEM_F);
    cudaFuncSetAttribute(k_gemm_t<true>,  cudaFuncAttributeMaxDynamicSharedMemorySize, GEMM_SMEM_H);
    cudaFuncSetAttribute(k_cls_bn, cudaFuncAttributeMaxDynamicSharedMemorySize, CLS_SMEM);

    const int edgeBlocks = (EE + 255) / 256;
    const int gemmGrid   = (NN + 127) / 128;    // 782
    const int vecBlocks  = (NN * 32) / 256;     // 12500

    // graph build (deg/fill pre-zeroed: load-time init + scan-tail rezero)
    k_degree<<<edgeBlocks, 256>>>(ei);
    k_scan_fused<<<SCANB, 256>>>();
    k_fill<<<edgeBlocks, 256>>>(ei);

    // layer 0: fc -> bn0 -> relu ; x0 (fp16) doubles as h0 for SPMM1
    k_gemm_t<false><<<gemmGrid, 256, GEMM_SMEM_F>>>(x, fc_w, fc_b, bB, NN);
    k_bnprep<<<1, 128>>>(gamma, beta);
    k_bnfused<<<vecBlocks, 256>>>((const float4*)bB, (const uint2*)0, (uint2*)x0h, NN * 32);

    for (int i = 0; i < 3; ++i) {
        const __half* hin = (i == 0) ? x0h : hH;
        k_spmm<<<vecBlocks, 256>>>((const uint2*)hin, (uint2*)aggH);
        k_gemm_t<true><<<gemmGrid, 256, GEMM_SMEM_H>>>(aggH, conv_w + i * DH * DH,
                                                       conv_b + i * DH, bB, NN);
        k_bnprep<<<1, 128>>>(gamma + (i + 1) * DH, beta + (i + 1) * DH);
        if (i < 2)
            k_bnfused<<<vecBlocks, 256>>>((const float4*)bB, (const uint2*)x0h,
                                          (uint2*)hH, NN * 32);
    }

    // classifier with fused BN/ReLU/residual A-stage (uses layer-3 scale/shift)
    k_cls_bn<<<gemmGrid, 256, CLS_SMEM>>>(bB, (const uint2*)x0h, cls_w, cls_b, out, NN);
}